// round 1
// baseline (speedup 1.0000x reference)
#include <cuda_runtime.h>
#include <cuda_bf16.h>
#include <math_constants.h>

// Problem: B=4, T=4096, C=1024, H=64. Causal single-head attention.
// out = softmax(mask(scale * (x@Wq)(x@Wk)^T)) @ (x@Wv)

#define B_  4
#define T_  4096
#define C_  1024
#define H_  64
#define SCALE 0.125f   // 64^-0.5

// Scratch for projections (device globals: no allocation allowed in kernel_launch)
__device__ float g_q[B_ * T_ * H_];
__device__ float g_k[B_ * T_ * H_];
__device__ float g_v[B_ * T_ * H_];

// ---------------------------------------------------------------------------
// Projection GEMM: out[M=16384, 64] = x[16384, 1024] @ W[1024, 64]
// Grid: (M/64, 3)  -- y selects (q,k,v). Block: 256 threads, 64x64 tile,
// 4x4 micro-tile per thread, K chunk = 16.
// ---------------------------------------------------------------------------
__global__ __launch_bounds__(256)
void proj_kernel(const float* __restrict__ x,
                 const float* __restrict__ Wk,
                 const float* __restrict__ Wq,
                 const float* __restrict__ Wv)
{
    const float* W;
    float* out;
    if (blockIdx.y == 0)      { W = Wq; out = g_q; }
    else if (blockIdx.y == 1) { W = Wk; out = g_k; }
    else                      { W = Wv; out = g_v; }

    __shared__ float xs[16][68];   // [k][m], pad 68 floats (272B, 16B-aligned rows)
    __shared__ float ws[16][68];   // [k][n]

    const int tid = threadIdx.x;
    const int tx  = tid & 15;      // 0..15 -> n
    const int ty  = tid >> 4;      // 0..15 -> m
    const int m0  = blockIdx.x * 64;

    float acc[4][4];
#pragma unroll
    for (int i = 0; i < 4; i++)
#pragma unroll
        for (int j = 0; j < 4; j++) acc[i][j] = 0.f;

    for (int k0 = 0; k0 < C_; k0 += 16) {
        // Load x tile: 64 rows x 16 k  (256 float4, one per thread)
        {
            int row = tid >> 2;           // 0..63
            int c4  = (tid & 3) * 4;      // 0,4,8,12
            float4 v = *(const float4*)&x[(size_t)(m0 + row) * C_ + k0 + c4];
            xs[c4 + 0][row] = v.x;
            xs[c4 + 1][row] = v.y;
            xs[c4 + 2][row] = v.z;
            xs[c4 + 3][row] = v.w;
        }
        // Load W tile: 16 k x 64 n (256 float4)
        {
            int kr = tid >> 4;            // 0..15
            int c4 = (tid & 15) * 4;      // 0..60
            float4 v = *(const float4*)&W[(size_t)(k0 + kr) * H_ + c4];
            *(float4*)&ws[kr][c4] = v;
        }
        __syncthreads();

#pragma unroll
        for (int kk = 0; kk < 16; kk++) {
            float a[4], b[4];
#pragma unroll
            for (int i = 0; i < 4; i++) a[i] = xs[kk][ty * 4 + i];
#pragma unroll
            for (int j = 0; j < 4; j++) b[j] = ws[kk][tx * 4 + j];
#pragma unroll
            for (int i = 0; i < 4; i++)
#pragma unroll
                for (int j = 0; j < 4; j++)
                    acc[i][j] = fmaf(a[i], b[j], acc[i][j]);
        }
        __syncthreads();
    }

#pragma unroll
    for (int i = 0; i < 4; i++) {
        float4 v = make_float4(acc[i][0], acc[i][1], acc[i][2], acc[i][3]);
        *(float4*)&out[(size_t)(m0 + ty * 4 + i) * H_ + tx * 4] = v;
    }
}

// ---------------------------------------------------------------------------
// Flash attention (causal), fp32.
// Grid: (T/128 q-tiles, B). Block: 128 threads, one q-row per thread.
// Q row + O accumulator in registers (float4[16] each); K/V tiles (64x64) and
// the per-row score buffer in dynamic shared memory.
// ---------------------------------------------------------------------------
#define BQ 128
#define BK 64

__global__ __launch_bounds__(BQ)
void attn_kernel(float* __restrict__ out)
{
    extern __shared__ float sm[];
    float* Ks = sm;                    // 64*64
    float* Vs = sm + BK * H_;          // 64*64
    float* Ss = sm + 2 * BK * H_;      // 128 * 65 (padded rows)

    const int b  = blockIdx.y;
    const int qi = blockIdx.x;
    const int r  = threadIdx.x;        // q row within tile
    const int qrow = qi * BQ + r;

    const float* qptr = g_q + ((size_t)b * T_ + qrow) * H_;
    float4 q4[16];
#pragma unroll
    for (int i = 0; i < 16; i++) q4[i] = *(const float4*)&qptr[i * 4];

    float4 o4[16];
#pragma unroll
    for (int i = 0; i < 16; i++) o4[i] = make_float4(0.f, 0.f, 0.f, 0.f);

    float m = -CUDART_INF_F;
    float l = 0.f;

    const int nkt = 2 * qi + 2;        // kv tiles covering [0, qtile_end)
    const float* kbase_ptr = g_k + (size_t)b * T_ * H_;
    const float* vbase_ptr = g_v + (size_t)b * T_ * H_;

    for (int jt = 0; jt < nkt; jt++) {
        // Cooperative load of K,V tiles (1024 float4 each; 8 per thread)
        {
            const float4* ksrc = (const float4*)(kbase_ptr + (size_t)jt * BK * H_);
            const float4* vsrc = (const float4*)(vbase_ptr + (size_t)jt * BK * H_);
#pragma unroll
            for (int idx = r; idx < BK * H_ / 4; idx += BQ) {
                ((float4*)Ks)[idx] = ksrc[idx];
                ((float4*)Vs)[idx] = vsrc[idx];
            }
        }
        __syncthreads();

        const int kb = jt * BK;
        float tmax = -CUDART_INF_F;

        // S = scale * q . K^T  (row r private)
        for (int j = 0; j < BK; j++) {
            const float4* kj = (const float4*)&Ks[j * H_];
            float s = 0.f;
#pragma unroll
            for (int i = 0; i < 16; i++) {
                float4 kv = kj[i];
                s = fmaf(q4[i].x, kv.x, s);
                s = fmaf(q4[i].y, kv.y, s);
                s = fmaf(q4[i].z, kv.z, s);
                s = fmaf(q4[i].w, kv.w, s);
            }
            s *= SCALE;
            if (kb + j > qrow) s = -1e30f;   // causal mask
            Ss[r * (BK + 1) + j] = s;
            tmax = fmaxf(tmax, s);
        }

        const float mnew  = fmaxf(m, tmax);
        const float alpha = __expf(m - mnew);   // m=-inf first tile -> 0
        l *= alpha;
#pragma unroll
        for (int i = 0; i < 16; i++) {
            o4[i].x *= alpha; o4[i].y *= alpha;
            o4[i].z *= alpha; o4[i].w *= alpha;
        }

        float lsum = 0.f;
        for (int j = 0; j < BK; j++) {
            float p = __expf(Ss[r * (BK + 1) + j] - mnew);
            lsum += p;
            const float4* vj = (const float4*)&Vs[j * H_];
#pragma unroll
            for (int i = 0; i < 16; i++) {
                float4 vv = vj[i];
                o4[i].x = fmaf(p, vv.x, o4[i].x);
                o4[i].y = fmaf(p, vv.y, o4[i].y);
                o4[i].z = fmaf(p, vv.z, o4[i].z);
                o4[i].w = fmaf(p, vv.w, o4[i].w);
            }
        }
        l += lsum;
        m  = mnew;
        __syncthreads();   // protect K/V before next tile load
    }

    const float inv = 1.f / l;
    float* optr = out + ((size_t)b * T_ + qrow) * H_;
#pragma unroll
    for (int i = 0; i < 16; i++) {
        float4 v = make_float4(o4[i].x * inv, o4[i].y * inv,
                               o4[i].z * inv, o4[i].w * inv);
        *(float4*)&optr[i * 4] = v;
    }
}

// ---------------------------------------------------------------------------

extern "C" void kernel_launch(void* const* d_in, const int* in_sizes, int n_in,
                              void* d_out, int out_size)
{
    const float* x  = (const float*)d_in[0];
    const float* Wk = (const float*)d_in[1];
    const float* Wq = (const float*)d_in[2];
    const float* Wv = (const float*)d_in[3];
    float* out = (float*)d_out;

    // Projections: q, k, v
    proj_kernel<<<dim3((B_ * T_) / 64, 3), 256>>>(x, Wk, Wq, Wv);

    // Attention
    const int smem = (2 * BK * H_ + BQ * (BK + 1)) * (int)sizeof(float); // 66048 B
    cudaFuncSetAttribute(attn_kernel, cudaFuncAttributeMaxDynamicSharedMemorySize, smem);
    attn_kernel<<<dim3(T_ / BQ, B_), BQ, smem>>>(out);
}

// round 2
// speedup vs baseline: 2.1621x; 2.1621x over previous
#include <cuda_runtime.h>
#include <cuda_bf16.h>
#include <math_constants.h>

// Problem: B=4, T=4096, C=1024, H=64. Causal single-head attention.
// out = softmax(mask(scale * (x@Wq)(x@Wk)^T)) @ (x@Wv)

#define B_  4
#define T_  4096
#define C_  1024
#define H_  64
#define SCALE 0.125f   // 64^-0.5

// Scratch for projections (device globals: no allocation allowed in kernel_launch)
__device__ float g_q[B_ * T_ * H_];
__device__ float g_k[B_ * T_ * H_];
__device__ float g_v[B_ * T_ * H_];

// ---------------------------------------------------------------------------
// Projection GEMM: out[M=16384, 64] = x[16384, 1024] @ W[1024, 64]
// Grid: (M/64, 3)  -- y selects (q,k,v). Block: 256 threads, 64x64 tile,
// 4x4 micro-tile per thread, K chunk = 16.
// ---------------------------------------------------------------------------
__global__ __launch_bounds__(256)
void proj_kernel(const float* __restrict__ x,
                 const float* __restrict__ Wk,
                 const float* __restrict__ Wq,
                 const float* __restrict__ Wv)
{
    const float* W;
    float* out;
    if (blockIdx.y == 0)      { W = Wq; out = g_q; }
    else if (blockIdx.y == 1) { W = Wk; out = g_k; }
    else                      { W = Wv; out = g_v; }

    __shared__ float xs[16][68];   // [k][m]
    __shared__ float ws[16][68];   // [k][n]

    const int tid = threadIdx.x;
    const int tx  = tid & 15;      // 0..15 -> n
    const int ty  = tid >> 4;      // 0..15 -> m
    const int m0  = blockIdx.x * 64;

    float acc[4][4];
#pragma unroll
    for (int i = 0; i < 4; i++)
#pragma unroll
        for (int j = 0; j < 4; j++) acc[i][j] = 0.f;

    for (int k0 = 0; k0 < C_; k0 += 16) {
        {
            int row = tid >> 2;           // 0..63
            int c4  = (tid & 3) * 4;      // 0,4,8,12
            float4 v = *(const float4*)&x[(size_t)(m0 + row) * C_ + k0 + c4];
            xs[c4 + 0][row] = v.x;
            xs[c4 + 1][row] = v.y;
            xs[c4 + 2][row] = v.z;
            xs[c4 + 3][row] = v.w;
        }
        {
            int kr = tid >> 4;            // 0..15
            int c4 = (tid & 15) * 4;      // 0..60
            float4 v = *(const float4*)&W[(size_t)(k0 + kr) * H_ + c4];
            *(float4*)&ws[kr][c4] = v;
        }
        __syncthreads();

#pragma unroll
        for (int kk = 0; kk < 16; kk++) {
            float a[4], b[4];
#pragma unroll
            for (int i = 0; i < 4; i++) a[i] = xs[kk][ty * 4 + i];
#pragma unroll
            for (int j = 0; j < 4; j++) b[j] = ws[kk][tx * 4 + j];
#pragma unroll
            for (int i = 0; i < 4; i++)
#pragma unroll
                for (int j = 0; j < 4; j++)
                    acc[i][j] = fmaf(a[i], b[j], acc[i][j]);
        }
        __syncthreads();
    }

#pragma unroll
    for (int i = 0; i < 4; i++) {
        float4 v = make_float4(acc[i][0], acc[i][1], acc[i][2], acc[i][3]);
        *(float4*)&out[(size_t)(m0 + ty * 4 + i) * H_ + tx * 4] = v;
    }
}

// ---------------------------------------------------------------------------
// Flash attention (causal), fp32, GEMM-ified.
// Block: 256 threads (16x16), BQ=64, BK=64, 4x4 micro-tiles.
// Each block processes the q-tile PAIR (i, 63-i) for one batch -> every block
// does exactly 65 KV tiles (causal load balance). Grid = (32, B).
// ---------------------------------------------------------------------------
#define BQ 64
#define BK 64
#define PADS 65
#define NTHREADS 256

__global__ __launch_bounds__(NTHREADS)
void attn_kernel(float* __restrict__ out)
{
    extern __shared__ float sm[];
    float* Qs = sm;                  // [row][k]  64 x 65
    float* Ks = Qs + 64 * PADS;      // [key][k]  64 x 65
    float* Vs = Ks + 64 * PADS;      // [key][h]  64 x 65
    float* St = Vs + 64 * PADS;      // [key][row] 64 x 65 (S then P, transposed)
    float* mrow = St + 64 * PADS;    // [64]
    float* lrow = mrow + 64;         // [64]
    float* arow = lrow + 64;         // [64] alpha
    float* red  = arow + 64;         // [4][64] partial reductions

    const int b    = blockIdx.y;
    const int pair = blockIdx.x;     // 0..31
    const int tid  = threadIdx.x;
    const int tx   = tid & 15;       // key/h micro-tile
    const int ty   = tid >> 4;       // q-row micro-tile
    const int r0   = ty * 4;
    const int c0   = tx * 4;
    const int rr   = tid & 63;       // softmax: row owned
    const int part = tid >> 6;       // softmax: key quarter
    const int k0   = part * 16;

    const float* kbase = g_k + (size_t)b * T_ * H_;
    const float* vbase = g_v + (size_t)b * T_ * H_;
    const float* qbase = g_q + (size_t)b * T_ * H_;

    for (int side = 0; side < 2; side++) {
        const int qt = side ? (63 - pair) : pair;   // q-tile index 0..63
        const int q0 = qt * BQ;                     // global q row base
        const int ntile = qt + 1;

        __syncthreads();   // prior side's smem consumers done

        // Load Q tile -> Qs[row][k]
        for (int i = tid; i < 64 * 16; i += NTHREADS) {
            int row = i >> 4;
            int h0  = (i & 15) * 4;
            float4 v = *(const float4*)&qbase[(size_t)(q0 + row) * H_ + h0];
            Qs[row * PADS + h0 + 0] = v.x;
            Qs[row * PADS + h0 + 1] = v.y;
            Qs[row * PADS + h0 + 2] = v.z;
            Qs[row * PADS + h0 + 3] = v.w;
        }
        if (tid < 64) { mrow[tid] = -CUDART_INF_F; lrow[tid] = 0.f; }

        float o[4][4];
#pragma unroll
        for (int i = 0; i < 4; i++)
#pragma unroll
            for (int j = 0; j < 4; j++) o[i][j] = 0.f;

        for (int jt = 0; jt < ntile; jt++) {
            __syncthreads();   // Qs ready / prior tile consumers done

            // Load K,V tile jt
            for (int i = tid; i < 64 * 16; i += NTHREADS) {
                int row = i >> 4;
                int h0  = (i & 15) * 4;
                float4 kv = *(const float4*)&kbase[(size_t)(jt * BK + row) * H_ + h0];
                float4 vv = *(const float4*)&vbase[(size_t)(jt * BK + row) * H_ + h0];
                Ks[row * PADS + h0 + 0] = kv.x;
                Ks[row * PADS + h0 + 1] = kv.y;
                Ks[row * PADS + h0 + 2] = kv.z;
                Ks[row * PADS + h0 + 3] = kv.w;
                Vs[row * PADS + h0 + 0] = vv.x;
                Vs[row * PADS + h0 + 1] = vv.y;
                Vs[row * PADS + h0 + 2] = vv.z;
                Vs[row * PADS + h0 + 3] = vv.w;
            }
            __syncthreads();

            // ---- S GEMM: S[q][key] = Q . K^T ----
            float s[4][4];
#pragma unroll
            for (int i = 0; i < 4; i++)
#pragma unroll
                for (int j = 0; j < 4; j++) s[i][j] = 0.f;

#pragma unroll 4
            for (int k = 0; k < 64; k++) {
                float aq[4], bk[4];
#pragma unroll
                for (int i = 0; i < 4; i++) aq[i] = Qs[(r0 + i) * PADS + k];
#pragma unroll
                for (int j = 0; j < 4; j++) bk[j] = Ks[(c0 + j) * PADS + k];
#pragma unroll
                for (int i = 0; i < 4; i++)
#pragma unroll
                    for (int j = 0; j < 4; j++)
                        s[i][j] = fmaf(aq[i], bk[j], s[i][j]);
            }

            // scale + causal mask (only the diagonal tile needs masking)
            const bool diag = (jt == ntile - 1);
#pragma unroll
            for (int i = 0; i < 4; i++)
#pragma unroll
                for (int j = 0; j < 4; j++) {
                    float v = s[i][j] * SCALE;
                    if (diag && (jt * BK + c0 + j > q0 + r0 + i)) v = -1e30f;
                    St[(c0 + j) * PADS + r0 + i] = v;
                }
            __syncthreads();

            // ---- softmax stage 1: partial max over this thread's key quarter
            {
                float pm = -CUDART_INF_F;
#pragma unroll
                for (int j = 0; j < 16; j++)
                    pm = fmaxf(pm, St[(k0 + j) * PADS + rr]);
                red[part * 64 + rr] = pm;
            }
            __syncthreads();

            // ---- stage 2: combine -> mnew, alpha
            if (tid < 64) {
                float mold = mrow[tid];
                float mnew = fmaxf(fmaxf(red[tid], red[64 + tid]),
                                   fmaxf(red[128 + tid], red[192 + tid]));
                mnew = fmaxf(mold, mnew);
                float alpha = __expf(mold - mnew);
                mrow[tid] = mnew;
                arow[tid] = alpha;
                lrow[tid] *= alpha;
            }
            __syncthreads();

            // ---- stage 3: p = exp(s - mnew), partial sums; rescale O regs
            {
                float mnew = mrow[rr];
                float ps = 0.f;
#pragma unroll
                for (int j = 0; j < 16; j++) {
                    float p = __expf(St[(k0 + j) * PADS + rr] - mnew);
                    St[(k0 + j) * PADS + rr] = p;
                    ps += p;
                }
                red[part * 64 + rr] = ps;
            }
            {
                float al[4];
#pragma unroll
                for (int i = 0; i < 4; i++) al[i] = arow[r0 + i];
#pragma unroll
                for (int i = 0; i < 4; i++)
#pragma unroll
                    for (int j = 0; j < 4; j++) o[i][j] *= al[i];
            }
            __syncthreads();

            // ---- stage 4: accumulate l (runs alongside O GEMM)
            if (tid < 64)
                lrow[tid] += red[tid] + red[64 + tid] + red[128 + tid] + red[192 + tid];

            // ---- O GEMM: O[q][h] += P[q][key] . V[key][h]  (P is in St, transposed)
#pragma unroll 4
            for (int k = 0; k < 64; k++) {
                float ap[4], bv[4];
#pragma unroll
                for (int i = 0; i < 4; i++) ap[i] = St[k * PADS + r0 + i];
#pragma unroll
                for (int j = 0; j < 4; j++) bv[j] = Vs[k * PADS + c0 + j];
#pragma unroll
                for (int i = 0; i < 4; i++)
#pragma unroll
                    for (int j = 0; j < 4; j++)
                        o[i][j] = fmaf(ap[i], bv[j], o[i][j]);
            }
        }

        __syncthreads();   // lrow final

        // Write output: rows r0..r0+3, h cols c0..c0+3
#pragma unroll
        for (int i = 0; i < 4; i++) {
            float inv = 1.f / lrow[r0 + i];
            float4 v = make_float4(o[i][0] * inv, o[i][1] * inv,
                                   o[i][2] * inv, o[i][3] * inv);
            *(float4*)&out[((size_t)b * T_ + q0 + r0 + i) * H_ + c0] = v;
        }
    }
}

// ---------------------------------------------------------------------------

extern "C" void kernel_launch(void* const* d_in, const int* in_sizes, int n_in,
                              void* d_out, int out_size)
{
    const float* x  = (const float*)d_in[0];
    const float* Wk = (const float*)d_in[1];
    const float* Wq = (const float*)d_in[2];
    const float* Wv = (const float*)d_in[3];
    float* out = (float*)d_out;

    // Projections: q, k, v
    proj_kernel<<<dim3((B_ * T_) / 64, 3), 256>>>(x, Wk, Wq, Wv);

    // Attention: 32 balanced q-tile pairs x 4 batches
    const int smem = (4 * 64 * PADS + 3 * 64 + 4 * 64) * (int)sizeof(float); // ~68.4 KB
    cudaFuncSetAttribute(attn_kernel, cudaFuncAttributeMaxDynamicSharedMemorySize, smem);
    attn_kernel<<<dim3(32, B_), NTHREADS, smem>>>(out);
}

// round 3
// speedup vs baseline: 2.2238x; 1.0285x over previous
#include <cuda_runtime.h>
#include <cuda_bf16.h>
#include <math_constants.h>

// Problem: B=4, T=4096, C=1024, H=64. Causal single-head attention.
// out = softmax(mask(scale * (x@Wq)(x@Wk)^T)) @ (x@Wv)

#define B_  4
#define T_  4096
#define C_  1024
#define H_  64
#define SCALE 0.125f   // 64^-0.5

__device__ float g_q[B_ * T_ * H_];
__device__ float g_k[B_ * T_ * H_];
__device__ float g_v[B_ * T_ * H_];

// ---------------------------------------------------------------------------
// Projection GEMM: out[M=16384, 64] = x[16384, 1024] @ W[1024, 64]
// ---------------------------------------------------------------------------
__global__ __launch_bounds__(256)
void proj_kernel(const float* __restrict__ x,
                 const float* __restrict__ Wk,
                 const float* __restrict__ Wq,
                 const float* __restrict__ Wv)
{
    const float* W;
    float* out;
    if (blockIdx.y == 0)      { W = Wq; out = g_q; }
    else if (blockIdx.y == 1) { W = Wk; out = g_k; }
    else                      { W = Wv; out = g_v; }

    __shared__ float xs[16][68];   // [k][m]
    __shared__ float ws[16][68];   // [k][n]

    const int tid = threadIdx.x;
    const int tx  = tid & 15;
    const int ty  = tid >> 4;
    const int m0  = blockIdx.x * 64;

    float acc[4][4];
#pragma unroll
    for (int i = 0; i < 4; i++)
#pragma unroll
        for (int j = 0; j < 4; j++) acc[i][j] = 0.f;

    for (int k0 = 0; k0 < C_; k0 += 16) {
        {
            int row = tid >> 2;
            int c4  = (tid & 3) * 4;
            float4 v = *(const float4*)&x[(size_t)(m0 + row) * C_ + k0 + c4];
            xs[c4 + 0][row] = v.x;
            xs[c4 + 1][row] = v.y;
            xs[c4 + 2][row] = v.z;
            xs[c4 + 3][row] = v.w;
        }
        {
            int kr = tid >> 4;
            int c4 = (tid & 15) * 4;
            float4 v = *(const float4*)&W[(size_t)(k0 + kr) * H_ + c4];
            *(float4*)&ws[kr][c4] = v;
        }
        __syncthreads();

#pragma unroll
        for (int kk = 0; kk < 16; kk++) {
            float a[4], b[4];
#pragma unroll
            for (int i = 0; i < 4; i++) a[i] = xs[kk][ty * 4 + i];
#pragma unroll
            for (int j = 0; j < 4; j++) b[j] = ws[kk][tx * 4 + j];
#pragma unroll
            for (int i = 0; i < 4; i++)
#pragma unroll
                for (int j = 0; j < 4; j++)
                    acc[i][j] = fmaf(a[i], b[j], acc[i][j]);
        }
        __syncthreads();
    }

#pragma unroll
    for (int i = 0; i < 4; i++) {
        float4 v = make_float4(acc[i][0], acc[i][1], acc[i][2], acc[i][3]);
        *(float4*)&out[(size_t)(m0 + ty * 4 + i) * H_ + tx * 4] = v;
    }
}

// ---------------------------------------------------------------------------
// Flash attention (causal), fp32, vectorized smem + register softmax.
// Block: 256 threads (16x16), BQ=BK=64, 4x4 micro-tiles.
// Transposed operand layouts so every GEMM k-iter is 2x LDS.128 + 16 FFMA:
//   Qt[k][row], Kt[k][key], St[key][row] (P), Vs[key][h]; pad 68 (16B-aligned).
// Softmax: rows owned by 16-lane half-warps -> shfl reductions, m/l in regs.
// K/V tile register-prefetch (LDG issued one tile ahead).
// Each block does the q-tile pair (i, 63-i): exactly 65 KV tiles. Grid (32,B).
// ---------------------------------------------------------------------------
#define PADS 68
#define NTHREADS 256

__global__ __launch_bounds__(NTHREADS)
void attn_kernel(float* __restrict__ out)
{
    extern __shared__ float sm[];
    float* Qt = sm;                  // [k][row]  64 x 68
    float* Kt = Qt + 64 * PADS;      // [k][key]  64 x 68
    float* Vs = Kt + 64 * PADS;      // [key][h]  64 x 68
    float* St = Vs + 64 * PADS;      // [key][row] 64 x 68 (holds P)

    const int b    = blockIdx.y;
    const int pair = blockIdx.x;     // 0..31
    const int tid  = threadIdx.x;
    const int tx   = tid & 15;
    const int ty   = tid >> 4;
    const int r0   = ty * 4;
    const int c0   = tx * 4;

    // cooperative-load mapping: each thread owns (lkey, lh0) and 4 chunks
    const int lkey = tid & 63;            // 0..63
    const int lh0  = (tid >> 6) * 16;     // 0,16,32,48

    const float* kbase = g_k + (size_t)b * T_ * H_;
    const float* vbase = g_v + (size_t)b * T_ * H_;
    const float* qbase = g_q + (size_t)b * T_ * H_;

    for (int side = 0; side < 2; side++) {
        const int qt = side ? (63 - pair) : pair;
        const int q0 = qt * 64;
        const int ntile = qt + 1;

        __syncthreads();   // prior side's smem consumers done

        // Load Q tile transposed: Qt[h][row]
#pragma unroll
        for (int c = 0; c < 4; c++) {
            int h0 = lh0 + c * 4;
            float4 v = *(const float4*)&qbase[(size_t)(q0 + lkey) * H_ + h0];
            Qt[(h0 + 0) * PADS + lkey] = v.x;
            Qt[(h0 + 1) * PADS + lkey] = v.y;
            Qt[(h0 + 2) * PADS + lkey] = v.z;
            Qt[(h0 + 3) * PADS + lkey] = v.w;
        }

        float m[4], l[4];
        float o[4][4];
#pragma unroll
        for (int i = 0; i < 4; i++) {
            m[i] = -CUDART_INF_F;
            l[i] = 0.f;
#pragma unroll
            for (int j = 0; j < 4; j++) o[i][j] = 0.f;
        }

        // prefetch tile 0 into regs
        float4 kpre[4], vpre[4];
#pragma unroll
        for (int c = 0; c < 4; c++) {
            int h0 = lh0 + c * 4;
            kpre[c] = *(const float4*)&kbase[(size_t)lkey * H_ + h0];
            vpre[c] = *(const float4*)&vbase[(size_t)lkey * H_ + h0];
        }

        for (int jt = 0; jt < ntile; jt++) {
            __syncthreads();   // prior tile's consumers done (Kt/Vs/St free)

            // Store prefetched K (transposed) and V (direct)
#pragma unroll
            for (int c = 0; c < 4; c++) {
                int h0 = lh0 + c * 4;
                Kt[(h0 + 0) * PADS + lkey] = kpre[c].x;
                Kt[(h0 + 1) * PADS + lkey] = kpre[c].y;
                Kt[(h0 + 2) * PADS + lkey] = kpre[c].z;
                Kt[(h0 + 3) * PADS + lkey] = kpre[c].w;
                *(float4*)&Vs[lkey * PADS + h0] = vpre[c];
            }
            __syncthreads();   // K/V (and Q on jt==0) visible

            // issue prefetch for next tile
            if (jt + 1 < ntile) {
                const float* kn = kbase + (size_t)((jt + 1) * 64 + lkey) * H_;
                const float* vn = vbase + (size_t)((jt + 1) * 64 + lkey) * H_;
#pragma unroll
                for (int c = 0; c < 4; c++) {
                    int h0 = lh0 + c * 4;
                    kpre[c] = *(const float4*)&kn[h0];
                    vpre[c] = *(const float4*)&vn[h0];
                }
            }

            // ---- S GEMM: s[i][j] = sum_k Qt[k][r0+i] * Kt[k][c0+j]
            float s[4][4];
#pragma unroll
            for (int i = 0; i < 4; i++)
#pragma unroll
                for (int j = 0; j < 4; j++) s[i][j] = 0.f;

#pragma unroll 8
            for (int k = 0; k < 64; k++) {
                float4 aq = *(const float4*)&Qt[k * PADS + r0];
                float4 bk = *(const float4*)&Kt[k * PADS + c0];
                s[0][0] = fmaf(aq.x, bk.x, s[0][0]);
                s[0][1] = fmaf(aq.x, bk.y, s[0][1]);
                s[0][2] = fmaf(aq.x, bk.z, s[0][2]);
                s[0][3] = fmaf(aq.x, bk.w, s[0][3]);
                s[1][0] = fmaf(aq.y, bk.x, s[1][0]);
                s[1][1] = fmaf(aq.y, bk.y, s[1][1]);
                s[1][2] = fmaf(aq.y, bk.z, s[1][2]);
                s[1][3] = fmaf(aq.y, bk.w, s[1][3]);
                s[2][0] = fmaf(aq.z, bk.x, s[2][0]);
                s[2][1] = fmaf(aq.z, bk.y, s[2][1]);
                s[2][2] = fmaf(aq.z, bk.z, s[2][2]);
                s[2][3] = fmaf(aq.z, bk.w, s[2][3]);
                s[3][0] = fmaf(aq.w, bk.x, s[3][0]);
                s[3][1] = fmaf(aq.w, bk.y, s[3][1]);
                s[3][2] = fmaf(aq.w, bk.z, s[3][2]);
                s[3][3] = fmaf(aq.w, bk.w, s[3][3]);
            }

            // scale + causal mask (diagonal tile only)
            const bool diag = (jt == ntile - 1);
#pragma unroll
            for (int i = 0; i < 4; i++)
#pragma unroll
                for (int j = 0; j < 4; j++) {
                    float v = s[i][j] * SCALE;
                    if (diag && (jt * 64 + c0 + j > q0 + r0 + i)) v = -1e30f;
                    s[i][j] = v;
                }

            // ---- softmax: register + shfl (rows owned by 16-lane groups)
#pragma unroll
            for (int i = 0; i < 4; i++) {
                float rmax = fmaxf(fmaxf(s[i][0], s[i][1]),
                                   fmaxf(s[i][2], s[i][3]));
                rmax = fmaxf(rmax, __shfl_xor_sync(0xffffffffu, rmax, 8));
                rmax = fmaxf(rmax, __shfl_xor_sync(0xffffffffu, rmax, 4));
                rmax = fmaxf(rmax, __shfl_xor_sync(0xffffffffu, rmax, 2));
                rmax = fmaxf(rmax, __shfl_xor_sync(0xffffffffu, rmax, 1));

                float mnew  = fmaxf(m[i], rmax);
                float alpha = __expf(m[i] - mnew);
                m[i] = mnew;

                float p0 = __expf(s[i][0] - mnew);
                float p1 = __expf(s[i][1] - mnew);
                float p2 = __expf(s[i][2] - mnew);
                float p3 = __expf(s[i][3] - mnew);
                s[i][0] = p0; s[i][1] = p1; s[i][2] = p2; s[i][3] = p3;

                float rsum = (p0 + p1) + (p2 + p3);
                rsum += __shfl_xor_sync(0xffffffffu, rsum, 8);
                rsum += __shfl_xor_sync(0xffffffffu, rsum, 4);
                rsum += __shfl_xor_sync(0xffffffffu, rsum, 2);
                rsum += __shfl_xor_sync(0xffffffffu, rsum, 1);

                l[i] = l[i] * alpha + rsum;
                o[i][0] *= alpha; o[i][1] *= alpha;
                o[i][2] *= alpha; o[i][3] *= alpha;
            }

            // ---- store P transposed: St[key][row], float4 along rows
#pragma unroll
            for (int j = 0; j < 4; j++) {
                float4 pv = make_float4(s[0][j], s[1][j], s[2][j], s[3][j]);
                *(float4*)&St[(c0 + j) * PADS + r0] = pv;
            }
            __syncthreads();   // P visible

            // ---- O GEMM: o[i][j] += sum_k St[k][r0+i] * Vs[k][c0+j]
#pragma unroll 8
            for (int k = 0; k < 64; k++) {
                float4 ap = *(const float4*)&St[k * PADS + r0];
                float4 bv = *(const float4*)&Vs[k * PADS + c0];
                o[0][0] = fmaf(ap.x, bv.x, o[0][0]);
                o[0][1] = fmaf(ap.x, bv.y, o[0][1]);
                o[0][2] = fmaf(ap.x, bv.z, o[0][2]);
                o[0][3] = fmaf(ap.x, bv.w, o[0][3]);
                o[1][0] = fmaf(ap.y, bv.x, o[1][0]);
                o[1][1] = fmaf(ap.y, bv.y, o[1][1]);
                o[1][2] = fmaf(ap.y, bv.z, o[1][2]);
                o[1][3] = fmaf(ap.y, bv.w, o[1][3]);
                o[2][0] = fmaf(ap.z, bv.x, o[2][0]);
                o[2][1] = fmaf(ap.z, bv.y, o[2][1]);
                o[2][2] = fmaf(ap.z, bv.z, o[2][2]);
                o[2][3] = fmaf(ap.z, bv.w, o[2][3]);
                o[3][0] = fmaf(ap.w, bv.x, o[3][0]);
                o[3][1] = fmaf(ap.w, bv.y, o[3][1]);
                o[3][2] = fmaf(ap.w, bv.z, o[3][2]);
                o[3][3] = fmaf(ap.w, bv.w, o[3][3]);
            }
        }

        // write output (l replicated across the 16-lane row group)
#pragma unroll
        for (int i = 0; i < 4; i++) {
            float inv = 1.f / l[i];
            float4 v = make_float4(o[i][0] * inv, o[i][1] * inv,
                                   o[i][2] * inv, o[i][3] * inv);
            *(float4*)&out[((size_t)b * T_ + q0 + r0 + i) * H_ + c0] = v;
        }
    }
}

// ---------------------------------------------------------------------------

extern "C" void kernel_launch(void* const* d_in, const int* in_sizes, int n_in,
                              void* d_out, int out_size)
{
    const float* x  = (const float*)d_in[0];
    const float* Wk = (const float*)d_in[1];
    const float* Wq = (const float*)d_in[2];
    const float* Wv = (const float*)d_in[3];
    float* out = (float*)d_out;

    proj_kernel<<<dim3((B_ * T_) / 64, 3), 256>>>(x, Wk, Wq, Wv);

    const int smem = 4 * 64 * PADS * (int)sizeof(float); // 69632 B
    cudaFuncSetAttribute(attn_kernel, cudaFuncAttributeMaxDynamicSharedMemorySize, smem);
    attn_kernel<<<dim3(32, B_), NTHREADS, smem>>>(out);
}

// round 4
// speedup vs baseline: 2.8165x; 1.2665x over previous
#include <cuda_runtime.h>
#include <cuda_bf16.h>
#include <math_constants.h>
#include <cstdint>

// Problem: B=4, T=4096, C=1024, H=64. Causal single-head attention.
// out = softmax(mask(scale * (x@Wq)(x@Wk)^T)) @ (x@Wv)

#define B_  4
#define T_  4096
#define C_  1024
#define H_  64
#define SCALE 0.125f   // 64^-0.5

__device__ float g_q[B_ * T_ * H_];
__device__ float g_k[B_ * T_ * H_];
__device__ float g_v[B_ * T_ * H_];

// ---------------------------------------------------------------------------
// Projection GEMM (fp32, unchanged): out[16384,64] = x[16384,1024] @ W[1024,64]
// ---------------------------------------------------------------------------
__global__ __launch_bounds__(256)
void proj_kernel(const float* __restrict__ x,
                 const float* __restrict__ Wk,
                 const float* __restrict__ Wq,
                 const float* __restrict__ Wv)
{
    const float* W;
    float* out;
    if (blockIdx.y == 0)      { W = Wq; out = g_q; }
    else if (blockIdx.y == 1) { W = Wk; out = g_k; }
    else                      { W = Wv; out = g_v; }

    __shared__ float xs[16][68];
    __shared__ float ws[16][68];

    const int tid = threadIdx.x;
    const int tx  = tid & 15;
    const int ty  = tid >> 4;
    const int m0  = blockIdx.x * 64;

    float acc[4][4];
#pragma unroll
    for (int i = 0; i < 4; i++)
#pragma unroll
        for (int j = 0; j < 4; j++) acc[i][j] = 0.f;

    for (int k0 = 0; k0 < C_; k0 += 16) {
        {
            int row = tid >> 2;
            int c4  = (tid & 3) * 4;
            float4 v = *(const float4*)&x[(size_t)(m0 + row) * C_ + k0 + c4];
            xs[c4 + 0][row] = v.x;
            xs[c4 + 1][row] = v.y;
            xs[c4 + 2][row] = v.z;
            xs[c4 + 3][row] = v.w;
        }
        {
            int kr = tid >> 4;
            int c4 = (tid & 15) * 4;
            float4 v = *(const float4*)&W[(size_t)(k0 + kr) * H_ + c4];
            *(float4*)&ws[kr][c4] = v;
        }
        __syncthreads();

#pragma unroll
        for (int kk = 0; kk < 16; kk++) {
            float a[4], b[4];
#pragma unroll
            for (int i = 0; i < 4; i++) a[i] = xs[kk][ty * 4 + i];
#pragma unroll
            for (int j = 0; j < 4; j++) b[j] = ws[kk][tx * 4 + j];
#pragma unroll
            for (int i = 0; i < 4; i++)
#pragma unroll
                for (int j = 0; j < 4; j++)
                    acc[i][j] = fmaf(a[i], b[j], acc[i][j]);
        }
        __syncthreads();
    }

#pragma unroll
    for (int i = 0; i < 4; i++) {
        float4 v = make_float4(acc[i][0], acc[i][1], acc[i][2], acc[i][3]);
        *(float4*)&out[(size_t)(m0 + ty * 4 + i) * H_ + tx * 4] = v;
    }
}

// ---------------------------------------------------------------------------
// tf32 helpers (3xTF32: hi/lo split for fp32-level accuracy on tensor cores)
// ---------------------------------------------------------------------------
__device__ __forceinline__ uint32_t cvt_tf32(float x) {
    uint32_t r;
    asm("cvt.rna.tf32.f32 %0, %1;" : "=r"(r) : "f"(x));
    return r;
}
__device__ __forceinline__ void split_tf32(float x, uint32_t& hi, uint32_t& lo) {
    hi = cvt_tf32(x);
    lo = cvt_tf32(x - __uint_as_float(hi));
}
__device__ __forceinline__ void mma_m16n8k8(float c[4], const uint32_t a[4],
                                            const uint32_t b[2]) {
    asm volatile(
        "mma.sync.aligned.m16n8k8.row.col.f32.tf32.tf32.f32 "
        "{%0,%1,%2,%3}, {%4,%5,%6,%7}, {%8,%9}, {%0,%1,%2,%3};\n"
        : "+f"(c[0]), "+f"(c[1]), "+f"(c[2]), "+f"(c[3])
        : "r"(a[0]), "r"(a[1]), "r"(a[2]), "r"(a[3]),
          "r"(b[0]), "r"(b[1]));
}

// ---------------------------------------------------------------------------
// Flash attention (causal), 3xTF32 tensor-core.
// Block 256 threads = 8 warps. Warp w: row-group rg=w%4 (16 q-rows),
// n-half nh=w/4 (32 cols). Pair schedule: block does q-tiles (i, 63-i),
// exactly 65 KV tiles. Grid (32, B).
// smem layouts (ld=68 -> mma fragment access bank = lane: conflict-free):
//   Qs[qrow][h] (pre-scaled by SCALE), Ks[key][h], Vt[h][key], St[qrow][key].
// ---------------------------------------------------------------------------
#define PADS 68
#define NT 256

__global__ __launch_bounds__(NT)
void attn_kernel(float* __restrict__ out)
{
    extern __shared__ float sm[];
    float* Qs   = sm;                 // [64][68]
    float* Ks   = Qs + 64 * PADS;     // [64][68]
    float* Vt   = Ks + 64 * PADS;     // [64][68]  (h-major, key contiguous)
    float* St   = Vt + 64 * PADS;     // [64][68]  (P)
    float* redm = St + 64 * PADS;     // [2][64] partial max per n-half
    float* redl = redm + 128;         // [2][64] l partials (epilogue)

    const int b    = blockIdx.y;
    const int pair = blockIdx.x;      // 0..31
    const int tid  = threadIdx.x;
    const int wid  = tid >> 5;
    const int lane = tid & 31;
    const int g    = lane >> 2;       // 0..7 group
    const int tig  = lane & 3;        // 0..3 thread-in-group
    const int rg   = wid & 3;         // row group -> rows rg*16 .. +15
    const int nh   = wid >> 2;        // n half  -> cols nh*32 .. +31
    const int rlo  = rg * 16 + g;     // local q row of c0/c1
    const int rhi  = rlo + 8;         // local q row of c2/c3

    const float* kbase = g_k + (size_t)b * T_ * H_;
    const float* vbase = g_v + (size_t)b * T_ * H_;
    const float* qbase = g_q + (size_t)b * T_ * H_;

    for (int side = 0; side < 2; side++) {
        const int qt = side ? (63 - pair) : pair;
        const int q0 = qt * 64;
        const int ntile = qt + 1;

        __syncthreads();   // prior side's smem consumers done

        // Load Q tile (pre-scaled): Qs[row][h]
#pragma unroll
        for (int i = 0; i < 4; i++) {
            int chunk = tid + i * NT;          // 0..1023
            int row = chunk >> 4;
            int h0  = (chunk & 15) * 4;
            float4 v = *(const float4*)&qbase[(size_t)(q0 + row) * H_ + h0];
            v.x *= SCALE; v.y *= SCALE; v.z *= SCALE; v.w *= SCALE;
            *(float4*)&Qs[row * PADS + h0] = v;
        }

        float m[2], l[2];
        m[0] = m[1] = -CUDART_INF_F;
        l[0] = l[1] = 0.f;
        float o[4][4];                 // 4 n-frags x 4 c-regs
#pragma unroll
        for (int f = 0; f < 4; f++)
#pragma unroll
            for (int c = 0; c < 4; c++) o[f][c] = 0.f;

        // prefetch KV tile 0
        float4 kpre[4], vpre[4];
#pragma unroll
        for (int i = 0; i < 4; i++) {
            int chunk = tid + i * NT;
            int key = chunk >> 4;
            int h0  = (chunk & 15) * 4;
            kpre[i] = *(const float4*)&kbase[(size_t)key * H_ + h0];
            vpre[i] = *(const float4*)&vbase[(size_t)key * H_ + h0];
        }

        for (int jt = 0; jt < ntile; jt++) {
            __syncthreads();   // Ks/Vt/St consumers of prev tile done

            // store prefetched K (direct) and V (transposed)
#pragma unroll
            for (int i = 0; i < 4; i++) {
                int chunk = tid + i * NT;
                int key = chunk >> 4;
                int h0  = (chunk & 15) * 4;
                *(float4*)&Ks[key * PADS + h0] = kpre[i];
                Vt[(h0 + 0) * PADS + key] = vpre[i].x;
                Vt[(h0 + 1) * PADS + key] = vpre[i].y;
                Vt[(h0 + 2) * PADS + key] = vpre[i].z;
                Vt[(h0 + 3) * PADS + key] = vpre[i].w;
            }
            __syncthreads();   // K/V (and Qs on jt==0) visible

            // prefetch next KV tile
            if (jt + 1 < ntile) {
#pragma unroll
                for (int i = 0; i < 4; i++) {
                    int chunk = tid + i * NT;
                    int key = (jt + 1) * 64 + (chunk >> 4);
                    int h0  = (chunk & 15) * 4;
                    kpre[i] = *(const float4*)&kbase[(size_t)key * H_ + h0];
                    vpre[i] = *(const float4*)&vbase[(size_t)key * H_ + h0];
                }
            }

            // ---- S = Q.K^T on tensor cores (3xTF32), warp tile m16 x n32
            float s[4][4];
#pragma unroll
            for (int f = 0; f < 4; f++)
#pragma unroll
                for (int c = 0; c < 4; c++) s[f][c] = 0.f;

#pragma unroll
            for (int k0 = 0; k0 < 64; k0 += 8) {
                uint32_t ahi[4], alo[4];
                split_tf32(Qs[rlo * PADS + k0 + tig],     ahi[0], alo[0]);
                split_tf32(Qs[rhi * PADS + k0 + tig],     ahi[1], alo[1]);
                split_tf32(Qs[rlo * PADS + k0 + tig + 4], ahi[2], alo[2]);
                split_tf32(Qs[rhi * PADS + k0 + tig + 4], ahi[3], alo[3]);
#pragma unroll
                for (int f = 0; f < 4; f++) {
                    int n0 = nh * 32 + f * 8;
                    uint32_t bhi[2], blo[2];
                    split_tf32(Ks[(n0 + g) * PADS + k0 + tig],     bhi[0], blo[0]);
                    split_tf32(Ks[(n0 + g) * PADS + k0 + tig + 4], bhi[1], blo[1]);
                    mma_m16n8k8(s[f], ahi, bhi);
                    mma_m16n8k8(s[f], ahi, blo);
                    mma_m16n8k8(s[f], alo, bhi);
                }
            }

            // ---- causal mask (diagonal tile only; Q pre-scaled)
            if (jt == ntile - 1) {
                const int rglo = q0 + rlo, rghi = q0 + rhi;
                const int cb = jt * 64 + nh * 32;
#pragma unroll
                for (int f = 0; f < 4; f++) {
                    int c0 = cb + f * 8 + tig * 2;
                    if (c0 > rglo)     s[f][0] = -1e30f;
                    if (c0 + 1 > rglo) s[f][1] = -1e30f;
                    if (c0 > rghi)     s[f][2] = -1e30f;
                    if (c0 + 1 > rghi) s[f][3] = -1e30f;
                }
            }

            // ---- partial row max (this n-half), exchange via smem
            {
                float pmlo = -CUDART_INF_F, pmhi = -CUDART_INF_F;
#pragma unroll
                for (int f = 0; f < 4; f++) {
                    pmlo = fmaxf(pmlo, fmaxf(s[f][0], s[f][1]));
                    pmhi = fmaxf(pmhi, fmaxf(s[f][2], s[f][3]));
                }
                pmlo = fmaxf(pmlo, __shfl_xor_sync(0xffffffffu, pmlo, 1));
                pmlo = fmaxf(pmlo, __shfl_xor_sync(0xffffffffu, pmlo, 2));
                pmhi = fmaxf(pmhi, __shfl_xor_sync(0xffffffffu, pmhi, 1));
                pmhi = fmaxf(pmhi, __shfl_xor_sync(0xffffffffu, pmhi, 2));
                if (tig == 0) {
                    redm[nh * 64 + rlo] = pmlo;
                    redm[nh * 64 + rhi] = pmhi;
                }
            }
            __syncthreads();   // both halves' maxima visible

            float alpha[2];
            {
                float mn0 = fmaxf(m[0], fmaxf(redm[rlo], redm[64 + rlo]));
                float mn1 = fmaxf(m[1], fmaxf(redm[rhi], redm[64 + rhi]));
                alpha[0] = __expf(m[0] - mn0);
                alpha[1] = __expf(m[1] - mn1);
                m[0] = mn0; m[1] = mn1;
            }

            // ---- p = exp(s - m), partial l, rescale O, store P
            {
                float ps0 = 0.f, ps1 = 0.f;
#pragma unroll
                for (int f = 0; f < 4; f++) {
                    float p0 = __expf(s[f][0] - m[0]);
                    float p1 = __expf(s[f][1] - m[0]);
                    float p2 = __expf(s[f][2] - m[1]);
                    float p3 = __expf(s[f][3] - m[1]);
                    ps0 += p0 + p1;
                    ps1 += p2 + p3;
                    int n0 = nh * 32 + f * 8 + tig * 2;
                    *(float2*)&St[rlo * PADS + n0] = make_float2(p0, p1);
                    *(float2*)&St[rhi * PADS + n0] = make_float2(p2, p3);
                }
                ps0 += __shfl_xor_sync(0xffffffffu, ps0, 1);
                ps0 += __shfl_xor_sync(0xffffffffu, ps0, 2);
                ps1 += __shfl_xor_sync(0xffffffffu, ps1, 1);
                ps1 += __shfl_xor_sync(0xffffffffu, ps1, 2);
                l[0] = l[0] * alpha[0] + ps0;   // this n-half's partial l
                l[1] = l[1] * alpha[1] + ps1;
#pragma unroll
                for (int f = 0; f < 4; f++) {
                    o[f][0] *= alpha[0]; o[f][1] *= alpha[0];
                    o[f][2] *= alpha[1]; o[f][3] *= alpha[1];
                }
            }
            __syncthreads();   // full P tile visible

            // ---- O += P.V on tensor cores (3xTF32), warp tile m16 x n32(h)
#pragma unroll
            for (int k0 = 0; k0 < 64; k0 += 8) {
                uint32_t ahi[4], alo[4];
                split_tf32(St[rlo * PADS + k0 + tig],     ahi[0], alo[0]);
                split_tf32(St[rhi * PADS + k0 + tig],     ahi[1], alo[1]);
                split_tf32(St[rlo * PADS + k0 + tig + 4], ahi[2], alo[2]);
                split_tf32(St[rhi * PADS + k0 + tig + 4], ahi[3], alo[3]);
#pragma unroll
                for (int f = 0; f < 4; f++) {
                    int n0 = nh * 32 + f * 8;   // h columns
                    uint32_t bhi[2], blo[2];
                    split_tf32(Vt[(n0 + g) * PADS + k0 + tig],     bhi[0], blo[0]);
                    split_tf32(Vt[(n0 + g) * PADS + k0 + tig + 4], bhi[1], blo[1]);
                    mma_m16n8k8(o[f], ahi, bhi);
                    mma_m16n8k8(o[f], ahi, blo);
                    mma_m16n8k8(o[f], alo, bhi);
                }
            }
        }

        // ---- epilogue: combine l across n-halves, write out
        if (tig == 0) {
            redl[nh * 64 + rlo] = l[0];
            redl[nh * 64 + rhi] = l[1];
        }
        __syncthreads();
        {
            float inv0 = 1.f / (redl[rlo] + redl[64 + rlo]);
            float inv1 = 1.f / (redl[rhi] + redl[64 + rhi]);
            float* orow0 = out + ((size_t)b * T_ + q0 + rlo) * H_;
            float* orow1 = out + ((size_t)b * T_ + q0 + rhi) * H_;
#pragma unroll
            for (int f = 0; f < 4; f++) {
                int n0 = nh * 32 + f * 8 + tig * 2;
                *(float2*)&orow0[n0] = make_float2(o[f][0] * inv0, o[f][1] * inv0);
                *(float2*)&orow1[n0] = make_float2(o[f][2] * inv1, o[f][3] * inv1);
            }
        }
    }
}

// ---------------------------------------------------------------------------

extern "C" void kernel_launch(void* const* d_in, const int* in_sizes, int n_in,
                              void* d_out, int out_size)
{
    const float* x  = (const float*)d_in[0];
    const float* Wk = (const float*)d_in[1];
    const float* Wq = (const float*)d_in[2];
    const float* Wv = (const float*)d_in[3];
    float* out = (float*)d_out;

    proj_kernel<<<dim3((B_ * T_) / 64, 3), 256>>>(x, Wk, Wq, Wv);

    const int smem = (4 * 64 * PADS + 256) * (int)sizeof(float); // 70656 B
    cudaFuncSetAttribute(attn_kernel, cudaFuncAttributeMaxDynamicSharedMemorySize, smem);
    attn_kernel<<<dim3(32, B_), NT, smem>>>(out);
}

// round 6
// speedup vs baseline: 3.8448x; 1.3651x over previous
#include <cuda_runtime.h>
#include <math_constants.h>
#include <cstdint>

// Problem: B=4, T=4096, C=1024, H=64. Causal single-head attention.
// out = softmax(mask(scale * (x@Wq)(x@Wk)^T)) @ (x@Wv)

#define B_  4
#define T_  4096
#define C_  1024
#define H_  64
#define SCALE 0.125f   // 64^-0.5, folded into Wq during prep (exact pow2)

// tf32 hi/lo split storage (written by proj, read by attn)
__device__ float2 g_qhl[B_ * T_ * H_];   // [b*T+t][h]   (q pre-scaled)
__device__ float2 g_khl[B_ * T_ * H_];   // [b*T+t][h]
__device__ float2 g_vT [B_ * H_ * T_];   // [b][h][t]    (transposed for PV B-frags)
__device__ float2 g_wt [3 * H_ * C_];    // [p][n][k], p: 0=q(scaled),1=k,2=v

// ---------------------------------------------------------------------------
// helpers
// ---------------------------------------------------------------------------
__device__ __forceinline__ uint32_t cvt_tf32(float x) {
    uint32_t r;
    asm("cvt.rna.tf32.f32 %0, %1;" : "=r"(r) : "f"(x));
    return r;
}
__device__ __forceinline__ float2 split2(float x) {
    uint32_t hi = cvt_tf32(x);
    float fhi = __uint_as_float(hi);
    uint32_t lo = cvt_tf32(x - fhi);
    return make_float2(fhi, __uint_as_float(lo));
}
__device__ __forceinline__ void mma8(float c[4], const uint32_t a[4],
                                     uint32_t b0, uint32_t b1) {
    asm volatile(
        "mma.sync.aligned.m16n8k8.row.col.f32.tf32.tf32.f32 "
        "{%0,%1,%2,%3}, {%4,%5,%6,%7}, {%8,%9}, {%0,%1,%2,%3};\n"
        : "+f"(c[0]), "+f"(c[1]), "+f"(c[2]), "+f"(c[3])
        : "r"(a[0]), "r"(a[1]), "r"(a[2]), "r"(a[3]), "r"(b0), "r"(b1));
}
__device__ __forceinline__ uint32_t sptr(const void* p) {
    return (uint32_t)__cvta_generic_to_shared(p);
}
__device__ __forceinline__ void cp16(uint32_t s, const void* g) {
    asm volatile("cp.async.cg.shared.global [%0], [%1], 16;" :: "r"(s), "l"(g));
}
#define CP_COMMIT() asm volatile("cp.async.commit_group;")
#define CP_WAIT0()  asm volatile("cp.async.wait_group 0;" ::: "memory")

// ---------------------------------------------------------------------------
// prep: split W into tf32 hi/lo, transposed [n][k]; fold SCALE into Wq.
// grid 768 x 256 covers 3*64*1024 elements.
// ---------------------------------------------------------------------------
__global__ void prep_w(const float* __restrict__ Wq,
                       const float* __restrict__ Wk,
                       const float* __restrict__ Wv)
{
    int idx = blockIdx.x * 256 + threadIdx.x;     // 0..196607
    int p = idx >> 16;
    int r = idx & 65535;
    int k = r >> 6;
    int n = r & 63;
    const float* W = (p == 0) ? Wq : (p == 1 ? Wk : Wv);
    float v = W[k * 64 + n];
    if (p == 0) v *= SCALE;
    g_wt[p * 65536 + n * 1024 + k] = split2(v);
}

// ---------------------------------------------------------------------------
// Projection, 3xTF32 tensor cores, fused q/k/v.
// Block: 256 thr (8 warps), tile M=128 rows x N=192 (3x64). Warp: m16 x n192.
// K chunks of 32; x reg-prefetched + split in-block; W hi/lo via cp.async
// double buffer. Outputs written pre-split (hi,lo).
// ---------------------------------------------------------------------------
#define PW 34   // float2 row stride for 32-k chunks

__global__ __launch_bounds__(256)
void proj_kernel(const float* __restrict__ x)
{
    extern __shared__ float2 psm[];
    float2* xs  = psm;                 // [128][34]
    float2* ws0 = psm + 128 * PW;      // [192][34]
    float2* ws1 = ws0 + 192 * PW;

    const int tid  = threadIdx.x;
    const int wid  = tid >> 5;
    const int lane = tid & 31;
    const int g    = lane >> 2;
    const int tig  = lane & 3;
    const int m0   = blockIdx.x * 128;
    const int rlo  = wid * 16 + g;
    const int rhi  = rlo + 8;

    float c[24][4];
#pragma unroll
    for (int f = 0; f < 24; f++)
#pragma unroll
        for (int j = 0; j < 4; j++) c[f][j] = 0.f;

    // x prefetch (chunk 0)
    const int xrow = tid >> 1, xhalf = tid & 1;
    const float* xptr = x + (size_t)(m0 + xrow) * C_ + xhalf * 16;
    float4 xpre[4];
#pragma unroll
    for (int j = 0; j < 4; j++) xpre[j] = *(const float4*)(xptr + j * 4);

    // W cp.async chunk 0 -> ws0
#pragma unroll
    for (int i = 0; i < 12; i++) {
        int idx = tid + i * 256;           // 0..3071
        int n = idx >> 4, kp = idx & 15;
        cp16(sptr(ws0 + n * PW + kp * 2), g_wt + (size_t)n * 1024 + kp * 2);
    }
    CP_COMMIT();

    for (int kc = 0; kc < 32; kc++) {
        const float2* ws = (kc & 1) ? ws1 : ws0;
        CP_WAIT0();
        __syncthreads();                   // ws ready; xs consumers done

        // split & store x chunk
#pragma unroll
        for (int j = 0; j < 4; j++) {
            float2 e0 = split2(xpre[j].x);
            float2 e1 = split2(xpre[j].y);
            float2 e2 = split2(xpre[j].z);
            float2 e3 = split2(xpre[j].w);
            float4* d = (float4*)(xs + xrow * PW + xhalf * 16 + j * 4);
            d[0] = make_float4(e0.x, e0.y, e1.x, e1.y);
            d[1] = make_float4(e2.x, e2.y, e3.x, e3.y);
        }

        if (kc + 1 < 32) {
            const float* xn = xptr + (kc + 1) * 32;
#pragma unroll
            for (int j = 0; j < 4; j++) xpre[j] = *(const float4*)(xn + j * 4);
            float2* wsn = (kc & 1) ? ws0 : ws1;
#pragma unroll
            for (int i = 0; i < 12; i++) {
                int idx = tid + i * 256;
                int n = idx >> 4, kp = idx & 15;
                cp16(sptr(wsn + n * PW + kp * 2),
                     g_wt + (size_t)n * 1024 + (kc + 1) * 32 + kp * 2);
            }
            CP_COMMIT();
        }
        __syncthreads();                   // xs visible

#pragma unroll
        for (int k0 = 0; k0 < 32; k0 += 8) {
            uint32_t ahi[4], alo[4];
            {
                uint2 t;
                t = *(const uint2*)&xs[rlo * PW + k0 + tig];     ahi[0] = t.x; alo[0] = t.y;
                t = *(const uint2*)&xs[rhi * PW + k0 + tig];     ahi[1] = t.x; alo[1] = t.y;
                t = *(const uint2*)&xs[rlo * PW + k0 + tig + 4]; ahi[2] = t.x; alo[2] = t.y;
                t = *(const uint2*)&xs[rhi * PW + k0 + tig + 4]; ahi[3] = t.x; alo[3] = t.y;
            }
#pragma unroll
            for (int f = 0; f < 24; f++) {
                uint2 b0 = *(const uint2*)&ws[(f * 8 + g) * PW + k0 + tig];
                uint2 b1 = *(const uint2*)&ws[(f * 8 + g) * PW + k0 + tig + 4];
                mma8(c[f], ahi, b0.x, b1.x);
                mma8(c[f], ahi, b0.y, b1.y);
                mma8(c[f], alo, b0.x, b1.x);
            }
        }
    }

    // epilogue: split accumulators, write hi/lo
#pragma unroll
    for (int f = 0; f < 24; f++) {
        int p  = f >> 3;
        int hh = (f & 7) * 8 + tig * 2;
        float2 e0 = split2(c[f][0]);
        float2 e1 = split2(c[f][1]);
        float2 e2 = split2(c[f][2]);
        float2 e3 = split2(c[f][3]);
        if (p < 2) {
            float2* basep = (p == 0) ? g_qhl : g_khl;
            *(float4*)(basep + (size_t)(m0 + rlo) * 64 + hh) =
                make_float4(e0.x, e0.y, e1.x, e1.y);
            *(float4*)(basep + (size_t)(m0 + rhi) * 64 + hh) =
                make_float4(e2.x, e2.y, e3.x, e3.y);
        } else {
            int r0g = m0 + rlo, bb0 = r0g >> 12, t0 = r0g & 4095;
            int r1g = m0 + rhi, bb1 = r1g >> 12, t1 = r1g & 4095;
            g_vT[(size_t)bb0 * 262144 + (size_t)hh * 4096 + t0]       = e0;
            g_vT[(size_t)bb0 * 262144 + (size_t)(hh + 1) * 4096 + t0] = e1;
            g_vT[(size_t)bb1 * 262144 + (size_t)hh * 4096 + t1]       = e2;
            g_vT[(size_t)bb1 * 262144 + (size_t)(hh + 1) * 4096 + t1] = e3;
        }
    }
}

// ---------------------------------------------------------------------------
// Flash attention (causal), tensor cores. S: 3xTF32 from pre-split q/k.
// PV: 2-term (P tf32 once; same value used in l -> rounding cancels).
// Block 256 thr = 8 warps, warp m16 x n32. Q frags in regs. K/V cp.async
// double-buffered (straight copies; V pre-transposed in gmem).
// Pair schedule (i, 63-i): 65 tiles per block. Grid (32, B).
// ---------------------------------------------------------------------------
#define AS 68    // float2 / u32 row stride

__device__ __forceinline__ void issue_kv(const float2* kb, const float2* vb,
                                         int jt, float2* Ks, float2* Vt, int tid)
{
#pragma unroll
    for (int i = 0; i < 8; i++) {
        int c = tid + i * 256;            // 0..2047
        int r = c >> 5, q = c & 31;
        cp16(sptr(Ks + r * AS + q * 2), kb + (size_t)(jt * 64 + r) * 64 + q * 2);
        cp16(sptr(Vt + r * AS + q * 2), vb + (size_t)r * 4096 + jt * 64 + q * 2);
    }
}

__global__ __launch_bounds__(256)
void attn_kernel(float* __restrict__ out)
{
    extern __shared__ float2 smp[];
    float2* smA = smp;                 // Q stage (f2) then St (u32 overlay)
    float2* Ks0 = smA + 64 * AS;
    float2* Vt0 = Ks0 + 64 * AS;
    float2* Ks1 = Vt0 + 64 * AS;
    float2* Vt1 = Ks1 + 64 * AS;
    float*  redm = (float*)(Vt1 + 64 * AS);   // [2][64]
    float*  redl = redm + 128;                // [2][64]
    uint32_t* stp = (uint32_t*)smA;           // St[row][key], stride AS

    const int b    = blockIdx.y;
    const int pair = blockIdx.x;
    const int tid  = threadIdx.x;
    const int wid  = tid >> 5;
    const int lane = tid & 31;
    const int g    = lane >> 2;
    const int tig  = lane & 3;
    const int rg   = wid & 3;
    const int nh   = wid >> 2;
    const int rlo  = rg * 16 + g;
    const int rhi  = rlo + 8;

    const float2* kb = g_khl + (size_t)b * T_ * 64;
    const float2* vb = g_vT  + (size_t)b * 64 * T_;
    const float2* qb = g_qhl + (size_t)b * T_ * 64;

    for (int side = 0; side < 2; side++) {
        const int qt = side ? (63 - pair) : pair;
        const int q0 = qt * 64;
        const int ntile = qt + 1;

        __syncthreads();   // prior side's smem consumers done

        // stage Q (cp.async) + KV tile 0
#pragma unroll
        for (int i = 0; i < 8; i++) {
            int c = tid + i * 256;
            int r = c >> 5, q = c & 31;
            cp16(sptr(smA + r * AS + q * 2), qb + (size_t)(q0 + r) * 64 + q * 2);
        }
        issue_kv(kb, vb, 0, Ks0, Vt0, tid);
        CP_COMMIT();
        CP_WAIT0();
        __syncthreads();

        // Q fragments -> registers (whole side)
        uint32_t qhi[8][4], qlo[8][4];
#pragma unroll
        for (int i = 0; i < 8; i++) {
            int k0 = i * 8;
            uint2 t;
            t = *(const uint2*)&smA[rlo * AS + k0 + tig];     qhi[i][0] = t.x; qlo[i][0] = t.y;
            t = *(const uint2*)&smA[rhi * AS + k0 + tig];     qhi[i][1] = t.x; qlo[i][1] = t.y;
            t = *(const uint2*)&smA[rlo * AS + k0 + tig + 4]; qhi[i][2] = t.x; qlo[i][2] = t.y;
            t = *(const uint2*)&smA[rhi * AS + k0 + tig + 4]; qhi[i][3] = t.x; qlo[i][3] = t.y;
        }

        float m[2], l[2];
        m[0] = m[1] = -CUDART_INF_F;
        l[0] = l[1] = 0.f;
        float o[4][4];
#pragma unroll
        for (int f = 0; f < 4; f++)
#pragma unroll
            for (int j = 0; j < 4; j++) o[f][j] = 0.f;

        for (int jt = 0; jt < ntile; jt++) {
            CP_WAIT0();
            __syncthreads();    // KV[jt&1] ready; prev St consumed; Q frags read

            const float2* Kst = (jt & 1) ? Ks1 : Ks0;
            const float2* Vtt = (jt & 1) ? Vt1 : Vt0;
            if (jt + 1 < ntile) {
                issue_kv(kb, vb, jt + 1, (jt & 1) ? Ks0 : Ks1,
                         (jt & 1) ? Vt0 : Vt1, tid);
                CP_COMMIT();
            }

            // ---- S = Q.K^T (3xTF32)
            float s[4][4];
#pragma unroll
            for (int f = 0; f < 4; f++)
#pragma unroll
                for (int j = 0; j < 4; j++) s[f][j] = 0.f;

#pragma unroll
            for (int i = 0; i < 8; i++) {
                int k0 = i * 8;
#pragma unroll
                for (int f = 0; f < 4; f++) {
                    int n0 = nh * 32 + f * 8;
                    uint2 b0 = *(const uint2*)&Kst[(n0 + g) * AS + k0 + tig];
                    uint2 b1 = *(const uint2*)&Kst[(n0 + g) * AS + k0 + tig + 4];
                    mma8(s[f], qhi[i], b0.x, b1.x);
                    mma8(s[f], qhi[i], b0.y, b1.y);
                    mma8(s[f], qlo[i], b0.x, b1.x);
                }
            }

            // ---- causal mask (diagonal tile only; scale already folded)
            if (jt == ntile - 1) {
                const int rglo = q0 + rlo, rghi = q0 + rhi;
                const int cb = jt * 64 + nh * 32;
#pragma unroll
                for (int f = 0; f < 4; f++) {
                    int c0 = cb + f * 8 + tig * 2;
                    if (c0 > rglo)     s[f][0] = -1e30f;
                    if (c0 + 1 > rglo) s[f][1] = -1e30f;
                    if (c0 > rghi)     s[f][2] = -1e30f;
                    if (c0 + 1 > rghi) s[f][3] = -1e30f;
                }
            }

            // ---- partial row max, exchange across n-halves
            {
                float pmlo = -CUDART_INF_F, pmhi = -CUDART_INF_F;
#pragma unroll
                for (int f = 0; f < 4; f++) {
                    pmlo = fmaxf(pmlo, fmaxf(s[f][0], s[f][1]));
                    pmhi = fmaxf(pmhi, fmaxf(s[f][2], s[f][3]));
                }
                pmlo = fmaxf(pmlo, __shfl_xor_sync(0xffffffffu, pmlo, 1));
                pmlo = fmaxf(pmlo, __shfl_xor_sync(0xffffffffu, pmlo, 2));
                pmhi = fmaxf(pmhi, __shfl_xor_sync(0xffffffffu, pmhi, 1));
                pmhi = fmaxf(pmhi, __shfl_xor_sync(0xffffffffu, pmhi, 2));
                if (tig == 0) {
                    redm[nh * 64 + rlo] = pmlo;
                    redm[nh * 64 + rhi] = pmhi;
                }
            }
            __syncthreads();

            float alpha0, alpha1;
            {
                float mn0 = fmaxf(m[0], fmaxf(redm[rlo], redm[64 + rlo]));
                float mn1 = fmaxf(m[1], fmaxf(redm[rhi], redm[64 + rhi]));
                alpha0 = __expf(m[0] - mn0);
                alpha1 = __expf(m[1] - mn1);
                m[0] = mn0; m[1] = mn1;
            }

            // ---- p = exp(s-m) -> tf32 (used for BOTH numerator and l),
            //      store to St, partial sums, rescale O
            {
                float ps0 = 0.f, ps1 = 0.f;
#pragma unroll
                for (int f = 0; f < 4; f++) {
                    uint32_t u0 = cvt_tf32(__expf(s[f][0] - m[0]));
                    uint32_t u1 = cvt_tf32(__expf(s[f][1] - m[0]));
                    uint32_t u2 = cvt_tf32(__expf(s[f][2] - m[1]));
                    uint32_t u3 = cvt_tf32(__expf(s[f][3] - m[1]));
                    ps0 += __uint_as_float(u0) + __uint_as_float(u1);
                    ps1 += __uint_as_float(u2) + __uint_as_float(u3);
                    int n0c = nh * 32 + f * 8 + tig * 2;
                    *(uint2*)&stp[rlo * AS + n0c] = make_uint2(u0, u1);
                    *(uint2*)&stp[rhi * AS + n0c] = make_uint2(u2, u3);
                }
                ps0 += __shfl_xor_sync(0xffffffffu, ps0, 1);
                ps0 += __shfl_xor_sync(0xffffffffu, ps0, 2);
                ps1 += __shfl_xor_sync(0xffffffffu, ps1, 1);
                ps1 += __shfl_xor_sync(0xffffffffu, ps1, 2);
                l[0] = l[0] * alpha0 + ps0;
                l[1] = l[1] * alpha1 + ps1;
#pragma unroll
                for (int f = 0; f < 4; f++) {
                    o[f][0] *= alpha0; o[f][1] *= alpha0;
                    o[f][2] *= alpha1; o[f][3] *= alpha1;
                }
            }
            __syncthreads();   // full P tile visible

            // ---- O += P.V (2-term: Phi*Vhi + Phi*Vlo)
#pragma unroll
            for (int i = 0; i < 8; i++) {
                int k0 = i * 8;
                uint32_t pa[4];
                pa[0] = stp[rlo * AS + k0 + tig];
                pa[1] = stp[rhi * AS + k0 + tig];
                pa[2] = stp[rlo * AS + k0 + tig + 4];
                pa[3] = stp[rhi * AS + k0 + tig + 4];
#pragma unroll
                for (int f = 0; f < 4; f++) {
                    int n0 = nh * 32 + f * 8;
                    uint2 b0 = *(const uint2*)&Vtt[(n0 + g) * AS + k0 + tig];
                    uint2 b1 = *(const uint2*)&Vtt[(n0 + g) * AS + k0 + tig + 4];
                    mma8(o[f], pa, b0.x, b1.x);
                    mma8(o[f], pa, b0.y, b1.y);
                }
            }
        }

        // ---- epilogue: combine l across n-halves, write out
        if (tig == 0) {
            redl[nh * 64 + rlo] = l[0];
            redl[nh * 64 + rhi] = l[1];
        }
        __syncthreads();
        {
            float inv0 = 1.f / (redl[rlo] + redl[64 + rlo]);
            float inv1 = 1.f / (redl[rhi] + redl[64 + rhi]);
            float* orow0 = out + ((size_t)b * T_ + q0 + rlo) * H_;
            float* orow1 = out + ((size_t)b * T_ + q0 + rhi) * H_;
#pragma unroll
            for (int f = 0; f < 4; f++) {
                int n0 = nh * 32 + f * 8 + tig * 2;
                *(float2*)&orow0[n0] = make_float2(o[f][0] * inv0, o[f][1] * inv0);
                *(float2*)&orow1[n0] = make_float2(o[f][2] * inv1, o[f][3] * inv1);
            }
        }
    }
}

// ---------------------------------------------------------------------------

extern "C" void kernel_launch(void* const* d_in, const int* in_sizes, int n_in,
                              void* d_out, int out_size)
{
    const float* x  = (const float*)d_in[0];
    const float* Wk = (const float*)d_in[1];
    const float* Wq = (const float*)d_in[2];
    const float* Wv = (const float*)d_in[3];
    float* out = (float*)d_out;

    prep_w<<<768, 256>>>(Wq, Wk, Wv);

    const int psmem = (128 * PW + 2 * 192 * PW) * (int)sizeof(float2); // 139264
    cudaFuncSetAttribute(proj_kernel, cudaFuncAttributeMaxDynamicSharedMemorySize, psmem);
    proj_kernel<<<128, 256, psmem>>>(x);

    const int asmem = 5 * 64 * AS * (int)sizeof(float2) + 256 * (int)sizeof(float); // 175104
    cudaFuncSetAttribute(attn_kernel, cudaFuncAttributeMaxDynamicSharedMemorySize, asmem);
    attn_kernel<<<dim3(32, B_), 256, asmem>>>(out);
}